// round 16
// baseline (speedup 1.0000x reference)
#include <cuda_runtime.h>
#include <cuda_bf16.h>
#include <math.h>
#include <stdint.h>

#define BATCH 4
#define SEQ   1024
#define QDIM  512
#define NH    8
#define HD    64
#define BH    (BATCH*NH)
#define OUT_ELEMS  (BATCH*SEQ*HD)
#define PROJ_ELEMS (BATCH*NH*SEQ*HD)
#define NROWS (BH*SEQ)
#define QCHUNKS 2
#define STR 20    // k-pair-major smem row stride (words)
#define TSTR 36   // natural-orientation smem row stride (words)

__device__ float g_q[PROJ_ELEMS];
__device__ float g_k[PROJ_ELEMS];
__device__ float g_v[PROJ_ELEMS];
__device__ float g_cpart[QCHUNKS*PROJ_ELEMS];
__device__ float g_partial[NROWS * 8];

// ---------------------------------------------------------------------------
// bf16 split helpers
// ---------------------------------------------------------------------------
__device__ __forceinline__ uint32_t packbf(float x, float y){
    __nv_bfloat162 t = __floats2bfloat162_rn(x, y);
    return *(uint32_t*)&t;
}
__device__ __forceinline__ void packsplit(float x, float y, uint32_t& hi, uint32_t& lo){
    __nv_bfloat16 xh = __float2bfloat16_rn(x);
    __nv_bfloat16 yh = __float2bfloat16_rn(y);
    __nv_bfloat162 h; h.x = xh; h.y = yh;
    hi = *(uint32_t*)&h;
    lo = packbf(x - __bfloat162float(xh), y - __bfloat162float(yh));
}
__device__ __forceinline__ void mmabf(float c[4], const uint32_t a[4], const uint32_t b[2]){
    asm volatile("mma.sync.aligned.m16n8k16.row.col.f32.bf16.bf16.f32 "
        "{%0,%1,%2,%3},{%4,%5,%6,%7},{%8,%9},{%0,%1,%2,%3};"
        : "+f"(c[0]),"+f"(c[1]),"+f"(c[2]),"+f"(c[3])
        : "r"(a[0]),"r"(a[1]),"r"(a[2]),"r"(a[3]),"r"(b[0]),"r"(b[1]));
}

__device__ __forceinline__ uint32_t smem_u32(const void* p){
    uint32_t a;
    asm("{.reg .u64 t; cvta.to.shared.u64 t, %1; cvt.u32.u64 %0, t;}" : "=r"(a) : "l"(p));
    return a;
}
// ---- k-pair-major (non-trans) loaders, stride STR ----
__device__ __forceinline__ void ldsmA(const uint32_t* S, int row0, int kp, uint32_t a[4]){
    int lane = threadIdx.x & 31;
    const uint32_t* p = S + (row0 + (lane & 15))*STR + kp + ((lane >> 4) << 2);
    uint32_t addr = smem_u32(p);
    asm volatile("ldmatrix.sync.aligned.m8n8.x4.shared.b16 {%0,%1,%2,%3}, [%4];"
        : "=r"(a[0]),"=r"(a[1]),"=r"(a[2]),"=r"(a[3]) : "r"(addr));
}
__device__ __forceinline__ void ldsmB2(const uint32_t* S, int n0, int kp,
                                       uint32_t b0[2], uint32_t b1[2]){
    int lane = threadIdx.x & 31;
    int row = n0 + ((lane >> 4) << 3) + (lane & 7);
    int ko  = kp + (((lane >> 3) & 1) << 2);
    uint32_t addr = smem_u32(S + row*STR + ko);
    asm volatile("ldmatrix.sync.aligned.m8n8.x4.shared.b16 {%0,%1,%2,%3}, [%4];"
        : "=r"(b0[0]),"=r"(b0[1]),"=r"(b1[0]),"=r"(b1[1]) : "r"(addr));
}
// ---- natural-orientation (trans) loaders, stride TSTR; memory rows = k ----
__device__ __forceinline__ void ldsmAT(const uint32_t* S, int k0, int m0, uint32_t a[4]){
    int lane = threadIdx.x & 31;
    int row  = k0 + (lane & 7) + ((lane & 16) >> 1);
    int woff = (m0 >> 1) + ((lane & 8) >> 1);
    uint32_t addr = smem_u32(S + row*TSTR + woff);
    asm volatile("ldmatrix.sync.aligned.m8n8.x4.trans.shared.b16 {%0,%1,%2,%3}, [%4];"
        : "=r"(a[0]),"=r"(a[1]),"=r"(a[2]),"=r"(a[3]) : "r"(addr));
}
__device__ __forceinline__ void ldsmBT2(const uint32_t* S, int k0, int n0,
                                        uint32_t b0[2], uint32_t b1[2]){
    int lane = threadIdx.x & 31;
    int row  = k0 + (lane & 7) + (lane & 8);
    int woff = (n0 >> 1) + ((lane & 16) >> 2);
    uint32_t addr = smem_u32(S + row*TSTR + woff);
    asm volatile("ldmatrix.sync.aligned.m8n8.x4.trans.shared.b16 {%0,%1,%2,%3}, [%4];"
        : "=r"(b0[0]),"=r"(b0[1]),"=r"(b1[0]),"=r"(b1[1]) : "r"(addr));
}

// ---------------------------------------------------------------------------
// Kernel 1: all three projections  Y = X @ W^T + b  (3-term bf16) -> [b,h,l,d]
// Block tile 64m x 64n, grid (8 heads, 64 m-tiles, 3 sel) = 1536 blocks.
// Double-buffered smem + register prefetch, ONE sync per k-step.
// ---------------------------------------------------------------------------
__global__ __launch_bounds__(256) void proj_all_kernel(
        const float* __restrict__ x0, const float* __restrict__ x1, const float* __restrict__ x2,
        const float* __restrict__ w0, const float* __restrict__ w1, const float* __restrict__ w2,
        const float* __restrict__ b0, const float* __restrict__ b1, const float* __restrict__ b2){
    __shared__ __align__(16) uint32_t Xhi[2][64*STR], Xlo[2][64*STR];
    __shared__ __align__(16) uint32_t Whi[2][64*STR], Wlo[2][64*STR];
    int sel = blockIdx.z;
    const float* X = sel==0 ? x0 : sel==1 ? x1 : x2;
    const float* W = sel==0 ? w0 : sel==1 ? w1 : w2;
    const float* bias = sel==0 ? b0 : sel==1 ? b1 : b2;
    float* dst = sel==0 ? g_q : sel==1 ? g_k : g_v;

    int tid = threadIdx.x;
    int h = blockIdx.x, n0 = h*64;
    int m0 = blockIdx.y*64;
    int w = tid>>5, wm = w>>1, wn = w&1;   // 4 x m16, 2 x n32
    int lane = tid&31, gr = lane>>2, c2 = (lane&3)*2;

    int lr = tid>>3, lc4 = tid&7;          // load row / col-quarter (64x32 tiles)
    float4 xr[2], wr[2];
    #define PRJ_LOAD(K0)                                                        \
        _Pragma("unroll")                                                       \
        for (int i=0;i<2;i++){                                                  \
            int r = lr + i*32;                                                  \
            xr[i] = *(const float4*)(X + (size_t)(m0+r)*QDIM + (K0) + lc4*4);   \
            wr[i] = *(const float4*)(W + (size_t)(n0+r)*QDIM + (K0) + lc4*4);   \
        }

    float acc[4][4] = {};
    PRJ_LOAD(0);
    int s = 0;
    for (int k0=0; k0<QDIM; k0+=32, s^=1){
        #pragma unroll
        for (int i=0;i<2;i++){
            int r = lr + i*32;
            uint32_t h0,l0,h1,l1;
            packsplit(xr[i].x, xr[i].y, h0, l0);
            packsplit(xr[i].z, xr[i].w, h1, l1);
            Xhi[s][r*STR + lc4*2] = h0; Xhi[s][r*STR + lc4*2+1] = h1;
            Xlo[s][r*STR + lc4*2] = l0; Xlo[s][r*STR + lc4*2+1] = l1;
            packsplit(wr[i].x, wr[i].y, h0, l0);
            packsplit(wr[i].z, wr[i].w, h1, l1);
            Whi[s][r*STR + lc4*2] = h0; Whi[s][r*STR + lc4*2+1] = h1;
            Wlo[s][r*STR + lc4*2] = l0; Wlo[s][r*STR + lc4*2+1] = l1;
        }
        __syncthreads();
        if (k0+32 < QDIM){ PRJ_LOAD(k0+32); }
        #pragma unroll
        for (int ks=0; ks<2; ks++){
            int kp = ks*8;
            uint32_t ah[4], al[4];
            ldsmA(Xhi[s], wm*16, kp, ah);
            ldsmA(Xlo[s], wm*16, kp, al);
            #pragma unroll
            for (int nj=0;nj<2;nj++){
                uint32_t bh0[2], bh1[2], bl0[2], bl1[2];
                ldsmB2(Whi[s], wn*32+nj*16, kp, bh0, bh1);
                ldsmB2(Wlo[s], wn*32+nj*16, kp, bl0, bl1);
                mmabf(acc[nj*2],   ah, bh0);
                mmabf(acc[nj*2],   ah, bl0);
                mmabf(acc[nj*2],   al, bh0);
                mmabf(acc[nj*2+1], ah, bh1);
                mmabf(acc[nj*2+1], ah, bl1);
                mmabf(acc[nj*2+1], al, bh1);
            }
        }
    }
    #undef PRJ_LOAD

    int b = m0>>10, l0 = m0&1023;
    float* base = dst + (size_t)(b*NH+h)*SEQ*HD;
    #pragma unroll
    for (int ni=0;ni<4;ni++){
        int row = l0 + wm*16 + gr;
        int col = wn*32 + ni*8 + c2;
        float2 bb = *(const float2*)(bias + n0 + col);
        float2 v0 = {acc[ni][0]+bb.x, acc[ni][1]+bb.y};
        float2 v1 = {acc[ni][2]+bb.x, acc[ni][3]+bb.y};
        *(float2*)(base + (size_t)row*HD + col) = v0;
        *(float2*)(base + (size_t)(row+8)*HD + col) = v1;
    }
}

// ---------------------------------------------------------------------------
// Kernel 2: P = exp(0.5 * Q K^T) (3-term bf16) -> attn (unnormalized) + partials
// grid (8 kb, 8 qb, 32 bh), 512 threads; P stores .cs
// ---------------------------------------------------------------------------
__global__ __launch_bounds__(512) void scores_exp_kernel(float* __restrict__ attn){
    __shared__ __align__(16) uint32_t Qhi[128*STR], Qlo[128*STR];
    __shared__ __align__(16) uint32_t Khi[128*STR], Klo[128*STR];
    __shared__ float sums[128][4];

    int tid = threadIdx.x;
    int kb = blockIdx.x, q0b = blockIdx.y*128, bh = blockIdx.z;
    int w = tid>>5, wq = w>>2, wk = w&3;
    int lane = tid&31, gr = lane>>2, c2 = (lane&3)*2;
    const float* Qg = g_q + (size_t)(bh*SEQ + q0b)*HD;
    const float* Kg = g_k + (size_t)(bh*SEQ + kb*128)*HD;

    float acc[2][4][4] = {};
    #pragma unroll
    for (int dt=0; dt<2; dt++){
        int d0 = dt*32;
        __syncthreads();
        #pragma unroll
        for (int i=0;i<2;i++){
            int lin = tid + i*512;
            int r = lin>>3, c4 = lin&7;
            float4 xq = *(const float4*)(Qg + (size_t)r*HD + d0 + c4*4);
            float4 xk = *(const float4*)(Kg + (size_t)r*HD + d0 + c4*4);
            uint32_t h0,l0,h1,l1;
            packsplit(xq.x, xq.y, h0, l0); packsplit(xq.z, xq.w, h1, l1);
            Qhi[r*STR + c4*2] = h0; Qhi[r*STR + c4*2+1] = h1;
            Qlo[r*STR + c4*2] = l0; Qlo[r*STR + c4*2+1] = l1;
            packsplit(xk.x, xk.y, h0, l0); packsplit(xk.z, xk.w, h1, l1);
            Khi[r*STR + c4*2] = h0; Khi[r*STR + c4*2+1] = h1;
            Klo[r*STR + c4*2] = l0; Klo[r*STR + c4*2+1] = l1;
        }
        __syncthreads();
        #pragma unroll
        for (int ks=0; ks<2; ks++){
            int kp = ks*8;
            uint32_t ah[2][4], al[2][4];
            #pragma unroll
            for (int mi=0;mi<2;mi++){
                ldsmA(Qhi, wq*32+mi*16, kp, ah[mi]);
                ldsmA(Qlo, wq*32+mi*16, kp, al[mi]);
            }
            #pragma unroll
            for (int nj=0;nj<2;nj++){
                uint32_t bh0_[2], bh1_[2], bl0_[2], bl1_[2];
                ldsmB2(Khi, wk*32+nj*16, kp, bh0_, bh1_);
                ldsmB2(Klo, wk*32+nj*16, kp, bl0_, bl1_);
                #pragma unroll
                for (int mi=0;mi<2;mi++){
                    mmabf(acc[mi][nj*2],   ah[mi], bh0_);
                    mmabf(acc[mi][nj*2],   ah[mi], bl0_);
                    mmabf(acc[mi][nj*2],   al[mi], bh0_);
                    mmabf(acc[mi][nj*2+1], ah[mi], bh1_);
                    mmabf(acc[mi][nj*2+1], ah[mi], bl1_);
                    mmabf(acc[mi][nj*2+1], al[mi], bh1_);
                }
            }
        }
    }

    float* Ab = attn + (size_t)bh*SEQ*SEQ;
    float rs[2][2] = {};
    #pragma unroll
    for (int mi=0;mi<2;mi++)
    #pragma unroll
    for (int ni=0;ni<4;ni++){
        float e0 = __expf(acc[mi][ni][0]*0.5f);
        float e1 = __expf(acc[mi][ni][1]*0.5f);
        float e2 = __expf(acc[mi][ni][2]*0.5f);
        float e3 = __expf(acc[mi][ni][3]*0.5f);
        int row = q0b + wq*32 + mi*16 + gr;
        int col = kb*128 + wk*32 + ni*8 + c2;
        float2 v0 = {e0, e1}, v1 = {e2, e3};
        __stcs((float2*)(Ab + (size_t)row*SEQ + col), v0);
        __stcs((float2*)(Ab + (size_t)(row+8)*SEQ + col), v1);
        rs[mi][0] += e0 + e1;
        rs[mi][1] += e2 + e3;
    }
    #pragma unroll
    for (int mi=0;mi<2;mi++)
    #pragma unroll
    for (int j=0;j<2;j++){
        float s = rs[mi][j];
        s += __shfl_xor_sync(0xffffffffu, s, 1);
        s += __shfl_xor_sync(0xffffffffu, s, 2);
        rs[mi][j] = s;
    }
    if ((lane&3)==0){
        #pragma unroll
        for (int mi=0;mi<2;mi++)
        #pragma unroll
        for (int j=0;j<2;j++)
            sums[wq*32 + mi*16 + gr + j*8][wk] = rs[mi][j];
    }
    __syncthreads();
    if (tid < 128){
        float t = sums[tid][0] + sums[tid][1] + sums[tid][2] + sums[tid][3];
        g_partial[(((size_t)bh*SEQ + q0b + tid)<<3) + kb] = t;
    }
}

// ---------------------------------------------------------------------------
// Kernel 3: normalize attn in place + PARTIAL context (3-term bf16)
// grid (16 n-tiles of 64, 32 bh, 2 q-chunks of 512), 256 threads.
// ---------------------------------------------------------------------------
__global__ __launch_bounds__(256) void context_norm_kernel(float* __restrict__ attn){
    __shared__ __align__(16) uint32_t Vhi[2][32*TSTR], Vlo[2][32*TSTR];
    __shared__ __align__(16) uint32_t Ahi[2][32*TSTR], Alo[2][32*TSTR];
    __shared__ float rinvS[SEQ/QCHUNKS];
    int tid = threadIdx.x;
    int nb = blockIdx.x*64, bh = blockIdx.y, qc = blockIdx.z;
    int w = tid>>5, wm = w>>1, wn = w&1;   // wm: 4 x m16 (d), wn: 2 x n32
    int lane = tid&31, gr = lane>>2, tc = lane&3;
    float* Ag = attn + (size_t)bh*SEQ*SEQ + nb;
    const float* Vg = g_v + (size_t)bh*SEQ*HD;

    int qlo = qc*(SEQ/QCHUNKS), qhi_ = qlo + SEQ/QCHUNKS;
    #pragma unroll
    for (int j=0;j<SEQ/QCHUNKS/256;j++){   // 1/S, identical fixed sum order
        int rr = tid + j*256;
        const float* p = g_partial + (((size_t)bh*SEQ + qlo + rr)<<3);
        float s = ((p[0]+p[1])+(p[2]+p[3])) + ((p[4]+p[5])+(p[6]+p[7]));
        rinvS[rr] = 1.0f / s;
    }
    __syncthreads();

    float4 vr[2], ar[2]; float ri[2];
    #define CTX_LOADS(Q0)                                                       \
        _Pragma("unroll")                                                       \
        for (int i=0;i<2;i++){                                                  \
            int idx = tid + i*256; int r = idx>>4, c4 = idx&15;                 \
            vr[i] = *(const float4*)(Vg + (size_t)((Q0)+r)*HD + c4*4);          \
            ar[i] = __ldcs((const float4*)(Ag + (size_t)((Q0)+r)*SEQ + c4*4));  \
            ri[i] = rinvS[(Q0)+r - qlo];                                        \
        }

    float acc[4][4] = {};
    CTX_LOADS(qlo);
    int s = 0;
    for (int q0=qlo; q0<qhi_; q0+=32, s^=1){
        #pragma unroll
        for (int i=0;i<2;i++){
            int idx = tid + i*256; int r = idx>>4, c4 = idx&15;
            uint32_t h0,l0,h1,l1;
            packsplit(vr[i].x, vr[i].y, h0, l0);
            packsplit(vr[i].z, vr[i].w, h1, l1);
            *(uint2*)&Vhi[s][r*TSTR + c4*2] = make_uint2(h0, h1);
            *(uint2*)&Vlo[s][r*TSTR + c4*2] = make_uint2(l0, l1);
            float4 a = ar[i]; float rv = ri[i];
            a.x*=rv; a.y*=rv; a.z*=rv; a.w*=rv;
            __stcs((float4*)(Ag + (size_t)(q0+r)*SEQ + c4*4), a);
            packsplit(a.x, a.y, h0, l0);
            packsplit(a.z, a.w, h1, l1);
            *(uint2*)&Ahi[s][r*TSTR + c4*2] = make_uint2(h0, h1);
            *(uint2*)&Alo[s][r*TSTR + c4*2] = make_uint2(l0, l1);
        }
        __syncthreads();
        if (q0+32 < qhi_){ CTX_LOADS(q0+32); }
        #pragma unroll
        for (int ks=0; ks<2; ks++){
            int k0 = ks*16;
            uint32_t ah[4], al[4];
            ldsmAT(Vhi[s], k0, wm*16, ah);
            ldsmAT(Vlo[s], k0, wm*16, al);
            #pragma unroll
            for (int nj=0;nj<2;nj++){
                uint32_t bh0_[2], bh1_[2], bl0_[2], bl1_[2];
                ldsmBT2(Ahi[s], k0, wn*32+nj*16, bh0_, bh1_);
                ldsmBT2(Alo[s], k0, wn*32+nj*16, bl0_, bl1_);
                mmabf(acc[nj*2],   ah, bh0_);
                mmabf(acc[nj*2],   ah, bl0_);
                mmabf(acc[nj*2],   al, bh0_);
                mmabf(acc[nj*2+1], ah, bh1_);
                mmabf(acc[nj*2+1], ah, bl1_);
                mmabf(acc[nj*2+1], al, bh1_);
            }
        }
    }
    #undef CTX_LOADS

    float* Cb = g_cpart + (size_t)qc*PROJ_ELEMS + (size_t)bh*SEQ*HD;
    #pragma unroll
    for (int ni=0;ni<4;ni++){
        int drow = wm*16 + gr;
        int col  = nb + wn*32 + ni*8 + tc*2;
        Cb[(size_t)col*HD + drow]         = acc[ni][0];
        Cb[(size_t)(col+1)*HD + drow]     = acc[ni][1];
        Cb[(size_t)col*HD + drow+8]       = acc[ni][2];
        Cb[(size_t)(col+1)*HD + drow+8]   = acc[ni][3];
    }
}

// ---------------------------------------------------------------------------
// Kernel 4: output = (sum of 2 ctx partials) @ wp^T + bp   (3-term bf16)
// block tile 32m x 64n -> grid 128 blocks, warps 2(m16) x 4(n16)
// Register prefetch of next C/W tiles during MMA phase.
// ---------------------------------------------------------------------------
__global__ __launch_bounds__(256) void outproj_kernel(const float* __restrict__ W,
        const float* __restrict__ bias, float* __restrict__ out){
    __shared__ __align__(16) uint32_t Chi[32*STR], Clo[32*STR];
    __shared__ __align__(16) uint32_t Whi[64*STR], Wlo[64*STR];
    int tid = threadIdx.x;
    int m0 = blockIdx.x*32;
    int b = m0>>10, l0 = m0&1023;
    int w = tid>>5, wm = w>>2, wn = w&3;   // 2 m16-tiles x 4 n16-tiles
    int lane = tid&31, gr = lane>>2, c2 = (lane&3)*2;

    int cr = tid>>3, cc4 = tid&7;          // C tile 32x32: one float4/thread
    float4 c0r, c1r, wvr[2];
    #define OPJ_LOAD(K0) {                                                      \
        int hh = (K0)>>6, off = (K0)&63;                                        \
        const float* Cg = g_cpart + ((size_t)(b*NH+hh)*SEQ + l0)*HD + off;      \
        size_t o = (size_t)cr*HD + cc4*4;                                       \
        c0r = *(const float4*)(Cg + o);                                         \
        c1r = *(const float4*)(Cg + (size_t)PROJ_ELEMS + o);                    \
        _Pragma("unroll")                                                       \
        for (int i=0;i<2;i++){                                                  \
            int lin = tid + i*256; int r = lin>>3, c4 = lin&7;                  \
            wvr[i] = *(const float4*)(W + (size_t)r*QDIM + (K0) + c4*4);        \
        }                                                                       \
    }

    float acc[2][4] = {};
    OPJ_LOAD(0);
    for (int k0=0; k0<QDIM; k0+=32){
        {
            float4 ss;
            ss.x = c0r.x+c1r.x; ss.y = c0r.y+c1r.y;
            ss.z = c0r.z+c1r.z; ss.w = c0r.w+c1r.w;
            uint32_t h0,l0_,h1,l1;
            packsplit(ss.x, ss.y, h0, l0_);
            packsplit(ss.z, ss.w, h1, l1);
            Chi[cr*STR + cc4*2] = h0; Chi[cr*STR + cc4*2+1] = h1;
            Clo[cr*STR + cc4*2] = l0_; Clo[cr*STR + cc4*2+1] = l1;
        }
        #pragma unroll
        for (int i=0;i<2;i++){
            int lin = tid + i*256;
            int r = lin>>3, c4 = lin&7;
            uint32_t h0,l0_,h1,l1;
            packsplit(wvr[i].x, wvr[i].y, h0, l0_);
            packsplit(wvr[i].z, wvr[i].w, h1, l1);
            Whi[r*STR + c4*2] = h0; Whi[r*STR + c4*2+1] = h1;
            Wlo[r*STR + c4*2] = l0_; Wlo[r*STR + c4*2+1] = l1;
        }
        __syncthreads();
        if (k0+32 < QDIM){ OPJ_LOAD(k0+32); }
        #pragma unroll
        for (int ks=0; ks<2; ks++){
            int kp = ks*8;
            uint32_t ah[4], al[4];
            ldsmA(Chi, wm*16, kp, ah);
            ldsmA(Clo, wm*16, kp, al);
            uint32_t bh0_[2], bh1_[2], bl0_[2], bl1_[2];
            ldsmB2(Whi, wn*16, kp, bh0_, bh1_);
            ldsmB2(Wlo, wn*16, kp, bl0_, bl1_);
            mmabf(acc[0], ah, bh0_);
            mmabf(acc[0], ah, bl0_);
            mmabf(acc[0], al, bh0_);
            mmabf(acc[1], ah, bh1_);
            mmabf(acc[1], ah, bl1_);
            mmabf(acc[1], al, bh1_);
        }
        __syncthreads();
    }
    #undef OPJ_LOAD

    #pragma unroll
    for (int ni=0;ni<2;ni++){
        int row = m0 + wm*16 + gr;
        int col = wn*16 + ni*8 + c2;
        float2 bb = *(const float2*)(bias + col);
        float2 v0 = {acc[ni][0]+bb.x, acc[ni][1]+bb.y};
        float2 v1 = {acc[ni][2]+bb.x, acc[ni][3]+bb.y};
        *(float2*)(out + (size_t)row*HD + col) = v0;
        *(float2*)(out + (size_t)(row+8)*HD + col) = v1;
    }
}

// ---------------------------------------------------------------------------
extern "C" void kernel_launch(void* const* d_in, const int* in_sizes, int n_in,
                              void* d_out, int out_size) {
    const float* q  = (const float*)d_in[0];
    const float* k  = (const float*)d_in[1];
    const float* v  = (const float*)d_in[2];
    const float* wq = (const float*)d_in[3];
    const float* bq = (const float*)d_in[4];
    const float* wk = (const float*)d_in[5];
    const float* bk = (const float*)d_in[6];
    const float* wv = (const float*)d_in[7];
    const float* bv = (const float*)d_in[8];
    const float* wp = (const float*)d_in[9];
    const float* bp = (const float*)d_in[10];

    float* out  = (float*)d_out;
    float* attn = out + OUT_ELEMS;

    dim3 projGrid(NH, (BATCH*SEQ)/64, 3);             // (8, 64, 3) = 1536 blocks
    proj_all_kernel<<<projGrid, 256>>>(q, k, v, wq, wk, wv, bq, bk, bv);

    dim3 scoreGrid(SEQ/128, SEQ/128, BH);             // (8, 8, 32)
    scores_exp_kernel<<<scoreGrid, 512>>>(attn);

    dim3 ctxGrid(SEQ/64, BH, QCHUNKS);                // (16, 32, 2)
    context_norm_kernel<<<ctxGrid, 256>>>(attn);

    outproj_kernel<<<(BATCH*SEQ)/32, 256>>>(wp, bp, out);  // 128 blocks
}

// round 17
// speedup vs baseline: 1.0417x; 1.0417x over previous
#include <cuda_runtime.h>
#include <cuda_bf16.h>
#include <math.h>
#include <stdint.h>

#define BATCH 4
#define SEQ   1024
#define QDIM  512
#define NH    8
#define HD    64
#define BH    (BATCH*NH)
#define OUT_ELEMS  (BATCH*SEQ*HD)
#define PROJ_ELEMS (BATCH*NH*SEQ*HD)
#define NROWS (BH*SEQ)
#define QCHUNKS 2
#define STR 20    // k-pair-major smem row stride (words)
#define TSTR 36   // natural-orientation smem row stride (words)

__device__ float g_q[PROJ_ELEMS];
__device__ float g_k[PROJ_ELEMS];
__device__ float g_v[PROJ_ELEMS];
__device__ float g_cpart[QCHUNKS*PROJ_ELEMS];
__device__ float g_partial[NROWS * 8];

// ---------------------------------------------------------------------------
// bf16 split helpers
// ---------------------------------------------------------------------------
__device__ __forceinline__ uint32_t packbf(float x, float y){
    __nv_bfloat162 t = __floats2bfloat162_rn(x, y);
    return *(uint32_t*)&t;
}
__device__ __forceinline__ void packsplit(float x, float y, uint32_t& hi, uint32_t& lo){
    __nv_bfloat16 xh = __float2bfloat16_rn(x);
    __nv_bfloat16 yh = __float2bfloat16_rn(y);
    __nv_bfloat162 h; h.x = xh; h.y = yh;
    hi = *(uint32_t*)&h;
    lo = packbf(x - __bfloat162float(xh), y - __bfloat162float(yh));
}
__device__ __forceinline__ void mmabf(float c[4], const uint32_t a[4], const uint32_t b[2]){
    asm volatile("mma.sync.aligned.m16n8k16.row.col.f32.bf16.bf16.f32 "
        "{%0,%1,%2,%3},{%4,%5,%6,%7},{%8,%9},{%0,%1,%2,%3};"
        : "+f"(c[0]),"+f"(c[1]),"+f"(c[2]),"+f"(c[3])
        : "r"(a[0]),"r"(a[1]),"r"(a[2]),"r"(a[3]),"r"(b[0]),"r"(b[1]));
}

__device__ __forceinline__ uint32_t smem_u32(const void* p){
    uint32_t a;
    asm("{.reg .u64 t; cvta.to.shared.u64 t, %1; cvt.u32.u64 %0, t;}" : "=r"(a) : "l"(p));
    return a;
}
// ---- k-pair-major (non-trans) loaders, stride STR ----
__device__ __forceinline__ void ldsmA(const uint32_t* S, int row0, int kp, uint32_t a[4]){
    int lane = threadIdx.x & 31;
    const uint32_t* p = S + (row0 + (lane & 15))*STR + kp + ((lane >> 4) << 2);
    uint32_t addr = smem_u32(p);
    asm volatile("ldmatrix.sync.aligned.m8n8.x4.shared.b16 {%0,%1,%2,%3}, [%4];"
        : "=r"(a[0]),"=r"(a[1]),"=r"(a[2]),"=r"(a[3]) : "r"(addr));
}
__device__ __forceinline__ void ldsmB2(const uint32_t* S, int n0, int kp,
                                       uint32_t b0[2], uint32_t b1[2]){
    int lane = threadIdx.x & 31;
    int row = n0 + ((lane >> 4) << 3) + (lane & 7);
    int ko  = kp + (((lane >> 3) & 1) << 2);
    uint32_t addr = smem_u32(S + row*STR + ko);
    asm volatile("ldmatrix.sync.aligned.m8n8.x4.shared.b16 {%0,%1,%2,%3}, [%4];"
        : "=r"(b0[0]),"=r"(b0[1]),"=r"(b1[0]),"=r"(b1[1]) : "r"(addr));
}
// ---- natural-orientation (trans) loaders, stride TSTR; memory rows = k ----
__device__ __forceinline__ void ldsmAT(const uint32_t* S, int k0, int m0, uint32_t a[4]){
    int lane = threadIdx.x & 31;
    int row  = k0 + (lane & 7) + ((lane & 16) >> 1);
    int woff = (m0 >> 1) + ((lane & 8) >> 1);
    uint32_t addr = smem_u32(S + row*TSTR + woff);
    asm volatile("ldmatrix.sync.aligned.m8n8.x4.trans.shared.b16 {%0,%1,%2,%3}, [%4];"
        : "=r"(a[0]),"=r"(a[1]),"=r"(a[2]),"=r"(a[3]) : "r"(addr));
}
__device__ __forceinline__ void ldsmBT2(const uint32_t* S, int k0, int n0,
                                        uint32_t b0[2], uint32_t b1[2]){
    int lane = threadIdx.x & 31;
    int row  = k0 + (lane & 7) + (lane & 8);
    int woff = (n0 >> 1) + ((lane & 16) >> 2);
    uint32_t addr = smem_u32(S + row*TSTR + woff);
    asm volatile("ldmatrix.sync.aligned.m8n8.x4.trans.shared.b16 {%0,%1,%2,%3}, [%4];"
        : "=r"(b0[0]),"=r"(b0[1]),"=r"(b1[0]),"=r"(b1[1]) : "r"(addr));
}

// ---------------------------------------------------------------------------
// Kernel 1: all three projections  Y = X @ W^T + b  (3-term bf16) -> [b,h,l,d]
// R15 tile (128m x 64n, grid (8,32,3)) + register prefetch of next k-step.
// ---------------------------------------------------------------------------
__global__ __launch_bounds__(256) void proj_all_kernel(
        const float* __restrict__ x0, const float* __restrict__ x1, const float* __restrict__ x2,
        const float* __restrict__ w0, const float* __restrict__ w1, const float* __restrict__ w2,
        const float* __restrict__ b0, const float* __restrict__ b1, const float* __restrict__ b2){
    __shared__ __align__(16) uint32_t Xhi[128*STR], Xlo[128*STR];
    __shared__ __align__(16) uint32_t Whi[64*STR],  Wlo[64*STR];
    int sel = blockIdx.z;
    const float* X = sel==0 ? x0 : sel==1 ? x1 : x2;
    const float* W = sel==0 ? w0 : sel==1 ? w1 : w2;
    const float* bias = sel==0 ? b0 : sel==1 ? b1 : b2;
    float* dst = sel==0 ? g_q : sel==1 ? g_k : g_v;

    int tid = threadIdx.x;
    int h = blockIdx.x, n0 = h*64;
    int m0 = blockIdx.y*128;
    int w = tid>>5, wm = w>>1, wn = w&1;
    int lane = tid&31, gr = lane>>2, c2 = (lane&3)*2;

    int lr = tid>>3, lc4 = tid&7;   // load indexing: row 0..31 (+i*32), col quarter
    float4 xr[4], wr[2];
    #define PRJ_LOAD(K0)                                                        \
        _Pragma("unroll")                                                       \
        for (int i=0;i<4;i++)                                                   \
            xr[i] = *(const float4*)(X + (size_t)(m0+lr+i*32)*QDIM + (K0) + lc4*4); \
        _Pragma("unroll")                                                       \
        for (int i=0;i<2;i++)                                                   \
            wr[i] = *(const float4*)(W + (size_t)(n0+lr+i*32)*QDIM + (K0) + lc4*4);

    float acc[2][4][4] = {};
    PRJ_LOAD(0);
    for (int k0=0; k0<QDIM; k0+=32){
        __syncthreads();   // previous MMA phase done; smem reusable
        #pragma unroll
        for (int i=0;i<4;i++){
            int r = lr + i*32;
            uint32_t h0,l0,h1,l1;
            packsplit(xr[i].x, xr[i].y, h0, l0);
            packsplit(xr[i].z, xr[i].w, h1, l1);
            Xhi[r*STR + lc4*2] = h0; Xhi[r*STR + lc4*2+1] = h1;
            Xlo[r*STR + lc4*2] = l0; Xlo[r*STR + lc4*2+1] = l1;
        }
        #pragma unroll
        for (int i=0;i<2;i++){
            int r = lr + i*32;
            uint32_t h0,l0,h1,l1;
            packsplit(wr[i].x, wr[i].y, h0, l0);
            packsplit(wr[i].z, wr[i].w, h1, l1);
            Whi[r*STR + lc4*2] = h0; Whi[r*STR + lc4*2+1] = h1;
            Wlo[r*STR + lc4*2] = l0; Wlo[r*STR + lc4*2+1] = l1;
        }
        __syncthreads();
        if (k0+32 < QDIM){ PRJ_LOAD(k0+32); }   // hide gmem under MMA phase
        #pragma unroll
        for (int ks=0; ks<2; ks++){
            int kp = ks*8;
            uint32_t ah[2][4], al[2][4];
            #pragma unroll
            for (int mi=0;mi<2;mi++){
                ldsmA(Xhi, wm*32+mi*16, kp, ah[mi]);
                ldsmA(Xlo, wm*32+mi*16, kp, al[mi]);
            }
            #pragma unroll
            for (int nj=0;nj<2;nj++){
                uint32_t bh0[2], bh1[2], bl0[2], bl1[2];
                ldsmB2(Whi, wn*32+nj*16, kp, bh0, bh1);
                ldsmB2(Wlo, wn*32+nj*16, kp, bl0, bl1);
                #pragma unroll
                for (int mi=0;mi<2;mi++){
                    mmabf(acc[mi][nj*2],   ah[mi], bh0);
                    mmabf(acc[mi][nj*2],   ah[mi], bl0);
                    mmabf(acc[mi][nj*2],   al[mi], bh0);
                    mmabf(acc[mi][nj*2+1], ah[mi], bh1);
                    mmabf(acc[mi][nj*2+1], ah[mi], bl1);
                    mmabf(acc[mi][nj*2+1], al[mi], bh1);
                }
            }
        }
    }
    #undef PRJ_LOAD

    int b = m0>>10, l0 = m0&1023;
    float* base = dst + (size_t)(b*NH+h)*SEQ*HD;
    #pragma unroll
    for (int mi=0;mi<2;mi++)
    #pragma unroll
    for (int ni=0;ni<4;ni++){
        int row = l0 + wm*32 + mi*16 + gr;
        int col = wn*32 + ni*8 + c2;
        float2 bb = *(const float2*)(bias + n0 + col);
        float2 v0 = {acc[mi][ni][0]+bb.x, acc[mi][ni][1]+bb.y};
        float2 v1 = {acc[mi][ni][2]+bb.x, acc[mi][ni][3]+bb.y};
        *(float2*)(base + (size_t)row*HD + col) = v0;
        *(float2*)(base + (size_t)(row+8)*HD + col) = v1;
    }
}

// ---------------------------------------------------------------------------
// Kernel 2: P = exp(0.5 * Q K^T) (3-term bf16) -> attn (unnormalized) + partials
// grid (8 kb, 8 qb, 32 bh), 512 threads; P stores .cs
// ---------------------------------------------------------------------------
__global__ __launch_bounds__(512) void scores_exp_kernel(float* __restrict__ attn){
    __shared__ __align__(16) uint32_t Qhi[128*STR], Qlo[128*STR];
    __shared__ __align__(16) uint32_t Khi[128*STR], Klo[128*STR];
    __shared__ float sums[128][4];

    int tid = threadIdx.x;
    int kb = blockIdx.x, q0b = blockIdx.y*128, bh = blockIdx.z;
    int w = tid>>5, wq = w>>2, wk = w&3;
    int lane = tid&31, gr = lane>>2, c2 = (lane&3)*2;
    const float* Qg = g_q + (size_t)(bh*SEQ + q0b)*HD;
    const float* Kg = g_k + (size_t)(bh*SEQ + kb*128)*HD;

    float acc[2][4][4] = {};
    #pragma unroll
    for (int dt=0; dt<2; dt++){
        int d0 = dt*32;
        __syncthreads();
        #pragma unroll
        for (int i=0;i<2;i++){
            int lin = tid + i*512;
            int r = lin>>3, c4 = lin&7;
            float4 xq = *(const float4*)(Qg + (size_t)r*HD + d0 + c4*4);
            float4 xk = *(const float4*)(Kg + (size_t)r*HD + d0 + c4*4);
            uint32_t h0,l0,h1,l1;
            packsplit(xq.x, xq.y, h0, l0); packsplit(xq.z, xq.w, h1, l1);
            Qhi[r*STR + c4*2] = h0; Qhi[r*STR + c4*2+1] = h1;
            Qlo[r*STR + c4*2] = l0; Qlo[r*STR + c4*2+1] = l1;
            packsplit(xk.x, xk.y, h0, l0); packsplit(xk.z, xk.w, h1, l1);
            Khi[r*STR + c4*2] = h0; Khi[r*STR + c4*2+1] = h1;
            Klo[r*STR + c4*2] = l0; Klo[r*STR + c4*2+1] = l1;
        }
        __syncthreads();
        #pragma unroll
        for (int ks=0; ks<2; ks++){
            int kp = ks*8;
            uint32_t ah[2][4], al[2][4];
            #pragma unroll
            for (int mi=0;mi<2;mi++){
                ldsmA(Qhi, wq*32+mi*16, kp, ah[mi]);
                ldsmA(Qlo, wq*32+mi*16, kp, al[mi]);
            }
            #pragma unroll
            for (int nj=0;nj<2;nj++){
                uint32_t bh0_[2], bh1_[2], bl0_[2], bl1_[2];
                ldsmB2(Khi, wk*32+nj*16, kp, bh0_, bh1_);
                ldsmB2(Klo, wk*32+nj*16, kp, bl0_, bl1_);
                #pragma unroll
                for (int mi=0;mi<2;mi++){
                    mmabf(acc[mi][nj*2],   ah[mi], bh0_);
                    mmabf(acc[mi][nj*2],   ah[mi], bl0_);
                    mmabf(acc[mi][nj*2],   al[mi], bh0_);
                    mmabf(acc[mi][nj*2+1], ah[mi], bh1_);
                    mmabf(acc[mi][nj*2+1], ah[mi], bl1_);
                    mmabf(acc[mi][nj*2+1], al[mi], bh1_);
                }
            }
        }
    }

    float* Ab = attn + (size_t)bh*SEQ*SEQ;
    float rs[2][2] = {};
    #pragma unroll
    for (int mi=0;mi<2;mi++)
    #pragma unroll
    for (int ni=0;ni<4;ni++){
        float e0 = __expf(acc[mi][ni][0]*0.5f);
        float e1 = __expf(acc[mi][ni][1]*0.5f);
        float e2 = __expf(acc[mi][ni][2]*0.5f);
        float e3 = __expf(acc[mi][ni][3]*0.5f);
        int row = q0b + wq*32 + mi*16 + gr;
        int col = kb*128 + wk*32 + ni*8 + c2;
        float2 v0 = {e0, e1}, v1 = {e2, e3};
        __stcs((float2*)(Ab + (size_t)row*SEQ + col), v0);
        __stcs((float2*)(Ab + (size_t)(row+8)*SEQ + col), v1);
        rs[mi][0] += e0 + e1;
        rs[mi][1] += e2 + e3;
    }
    #pragma unroll
    for (int mi=0;mi<2;mi++)
    #pragma unroll
    for (int j=0;j<2;j++){
        float s = rs[mi][j];
        s += __shfl_xor_sync(0xffffffffu, s, 1);
        s += __shfl_xor_sync(0xffffffffu, s, 2);
        rs[mi][j] = s;
    }
    if ((lane&3)==0){
        #pragma unroll
        for (int mi=0;mi<2;mi++)
        #pragma unroll
        for (int j=0;j<2;j++)
            sums[wq*32 + mi*16 + gr + j*8][wk] = rs[mi][j];
    }
    __syncthreads();
    if (tid < 128){
        float t = sums[tid][0] + sums[tid][1] + sums[tid][2] + sums[tid][3];
        g_partial[(((size_t)bh*SEQ + q0b + tid)<<3) + kb] = t;
    }
}

// ---------------------------------------------------------------------------
// Kernel 3: normalize attn in place + PARTIAL context (3-term bf16)
// grid (16 n-tiles of 64, 32 bh, 2 q-chunks of 512), 256 threads.
// ---------------------------------------------------------------------------
__global__ __launch_bounds__(256) void context_norm_kernel(float* __restrict__ attn){
    __shared__ __align__(16) uint32_t Vhi[2][32*TSTR], Vlo[2][32*TSTR];
    __shared__ __align__(16) uint32_t Ahi[2][32*TSTR], Alo[2][32*TSTR];
    __shared__ float rinvS[SEQ/QCHUNKS];
    int tid = threadIdx.x;
    int nb = blockIdx.x*64, bh = blockIdx.y, qc = blockIdx.z;
    int w = tid>>5, wm = w>>1, wn = w&1;   // wm: 4 x m16 (d), wn: 2 x n32
    int lane = tid&31, gr = lane>>2, tc = lane&3;
    float* Ag = attn + (size_t)bh*SEQ*SEQ + nb;
    const float* Vg = g_v + (size_t)bh*SEQ*HD;

    int qlo = qc*(SEQ/QCHUNKS), qhi_ = qlo + SEQ/QCHUNKS;
    #pragma unroll
    for (int j=0;j<SEQ/QCHUNKS/256;j++){   // 1/S, identical fixed sum order
        int rr = tid + j*256;
        const float* p = g_partial + (((size_t)bh*SEQ + qlo + rr)<<3);
        float s = ((p[0]+p[1])+(p[2]+p[3])) + ((p[4]+p[5])+(p[6]+p[7]));
        rinvS[rr] = 1.0f / s;
    }
    __syncthreads();

    float4 vr[2], ar[2]; float ri[2];
    #define CTX_LOADS(Q0)                                                       \
        _Pragma("unroll")                                                       \
        for (int i=0;i<2;i++){                                                  \
            int idx = tid + i*256; int r = idx>>4, c4 = idx&15;                 \
            vr[i] = *(const float4*)(Vg + (size_t)((Q0)+r)*HD + c4*4);          \
            ar[i] = __ldcs((const float4*)(Ag + (size_t)((Q0)+r)*SEQ + c4*4));  \
            ri[i] = rinvS[(Q0)+r - qlo];                                        \
        }

    float acc[4][4] = {};
    CTX_LOADS(qlo);
    int s = 0;
    for (int q0=qlo; q0<qhi_; q0+=32, s^=1){
        #pragma unroll
        for (int i=0;i<2;i++){
            int idx = tid + i*256; int r = idx>>4, c4 = idx&15;
            uint32_t h0,l0,h1,l1;
            packsplit(vr[i].x, vr[i].y, h0, l0);
            packsplit(vr[i].z, vr[i].w, h1, l1);
            *(uint2*)&Vhi[s][r*TSTR + c4*2] = make_uint2(h0, h1);
            *(uint2*)&Vlo[s][r*TSTR + c4*2] = make_uint2(l0, l1);
            float4 a = ar[i]; float rv = ri[i];
            a.x*=rv; a.y*=rv; a.z*=rv; a.w*=rv;
            __stcs((float4*)(Ag + (size_t)(q0+r)*SEQ + c4*4), a);
            packsplit(a.x, a.y, h0, l0);
            packsplit(a.z, a.w, h1, l1);
            *(uint2*)&Ahi[s][r*TSTR + c4*2] = make_uint2(h0, h1);
            *(uint2*)&Alo[s][r*TSTR + c4*2] = make_uint2(l0, l1);
        }
        __syncthreads();
        if (q0+32 < qhi_){ CTX_LOADS(q0+32); }
        #pragma unroll
        for (int ks=0; ks<2; ks++){
            int k0 = ks*16;
            uint32_t ah[4], al[4];
            ldsmAT(Vhi[s], k0, wm*16, ah);
            ldsmAT(Vlo[s], k0, wm*16, al);
            #pragma unroll
            for (int nj=0;nj<2;nj++){
                uint32_t bh0_[2], bh1_[2], bl0_[2], bl1_[2];
                ldsmBT2(Ahi[s], k0, wn*32+nj*16, bh0_, bh1_);
                ldsmBT2(Alo[s], k0, wn*32+nj*16, bl0_, bl1_);
                mmabf(acc[nj*2],   ah, bh0_);
                mmabf(acc[nj*2],   ah, bl0_);
                mmabf(acc[nj*2],   al, bh0_);
                mmabf(acc[nj*2+1], ah, bh1_);
                mmabf(acc[nj*2+1], ah, bl1_);
                mmabf(acc[nj*2+1], al, bh1_);
            }
        }
    }
    #undef CTX_LOADS

    float* Cb = g_cpart + (size_t)qc*PROJ_ELEMS + (size_t)bh*SEQ*HD;
    #pragma unroll
    for (int ni=0;ni<4;ni++){
        int drow = wm*16 + gr;
        int col  = nb + wn*32 + ni*8 + tc*2;
        Cb[(size_t)col*HD + drow]         = acc[ni][0];
        Cb[(size_t)(col+1)*HD + drow]     = acc[ni][1];
        Cb[(size_t)col*HD + drow+8]       = acc[ni][2];
        Cb[(size_t)(col+1)*HD + drow+8]   = acc[ni][3];
    }
}

// ---------------------------------------------------------------------------
// Kernel 4: output = (sum of 2 ctx partials) @ wp^T + bp   (3-term bf16)
// block tile 32m x 64n -> 128 blocks; register prefetch during MMA.
// ---------------------------------------------------------------------------
__global__ __launch_bounds__(256) void outproj_kernel(const float* __restrict__ W,
        const float* __restrict__ bias, float* __restrict__ out){
    __shared__ __align__(16) uint32_t Chi[32*STR], Clo[32*STR];
    __shared__ __align__(16) uint32_t Whi[64*STR], Wlo[64*STR];
    int tid = threadIdx.x;
    int m0 = blockIdx.x*32;
    int b = m0>>10, l0 = m0&1023;
    int w = tid>>5, wm = w>>2, wn = w&3;   // 2 m16-tiles x 4 n16-tiles
    int lane = tid&31, gr = lane>>2, c2 = (lane&3)*2;

    int cr = tid>>3, cc4 = tid&7;
    float4 c0r, c1r, wvr[2];
    #define OPJ_LOAD(K0) {                                                      \
        int hh = (K0)>>6, off = (K0)&63;                                        \
        const float* Cg = g_cpart + ((size_t)(b*NH+hh)*SEQ + l0)*HD + off;      \
        size_t o = (size_t)cr*HD + cc4*4;                                       \
        c0r = *(const float4*)(Cg + o);                                         \
        c1r = *(const float4*)(Cg + (size_t)PROJ_ELEMS + o);                    \
        _Pragma("unroll")                                                       \
        for (int i=0;i<2;i++){                                                  \
            int lin = tid + i*256; int r = lin>>3, c4 = lin&7;                  \
            wvr[i] = *(const float4*)(W + (size_t)r*QDIM + (K0) + c4*4);        \
        }                                                                       \
    }

    float acc[2][4] = {};
    OPJ_LOAD(0);
    for (int k0=0; k0<QDIM; k0+=32){
        {
            float4 ss;
            ss.x = c0r.x+c1r.x; ss.y = c0r.y+c1r.y;
            ss.z = c0r.z+c1r.z; ss.w = c0r.w+c1r.w;
            uint32_t h0,l0_,h1,l1;
            packsplit(ss.x, ss.y, h0, l0_);
            packsplit(ss.z, ss.w, h1, l1);
            Chi[cr*STR + cc4*2] = h0; Chi[cr*STR + cc4*2+1] = h1;
            Clo[cr*STR + cc4*2] = l0_; Clo[cr*STR + cc4*2+1] = l1;
        }
        #pragma unroll
        for (int i=0;i<2;i++){
            int lin = tid + i*256;
            int r = lin>>3, c4 = lin&7;
            uint32_t h0,l0_,h1,l1;
            packsplit(wvr[i].x, wvr[i].y, h0, l0_);
            packsplit(wvr[i].z, wvr[i].w, h1, l1);
            Whi[r*STR + c4*2] = h0; Whi[r*STR + c4*2+1] = h1;
            Wlo[r*STR + c4*2] = l0_; Wlo[r*STR + c4*2+1] = l1;
        }
        __syncthreads();
        if (k0+32 < QDIM){ OPJ_LOAD(k0+32); }
        #pragma unroll
        for (int ks=0; ks<2; ks++){
            int kp = ks*8;
            uint32_t ah[4], al[4];
            ldsmA(Chi, wm*16, kp, ah);
            ldsmA(Clo, wm*16, kp, al);
            uint32_t bh0_[2], bh1_[2], bl0_[2], bl1_[2];
            ldsmB2(Whi, wn*16, kp, bh0_, bh1_);
            ldsmB2(Wlo, wn*16, kp, bl0_, bl1_);
            mmabf(acc[0], ah, bh0_);
            mmabf(acc[0], ah, bl0_);
            mmabf(acc[0], al, bh0_);
            mmabf(acc[1], ah, bh1_);
            mmabf(acc[1], ah, bl1_);
            mmabf(acc[1], al, bh1_);
        }
        __syncthreads();
    }
    #undef OPJ_LOAD

    #pragma unroll
    for (int ni=0;ni<2;ni++){
        int row = m0 + wm*16 + gr;
        int col = wn*16 + ni*8 + c2;
        float2 bb = *(const float2*)(bias + col);
        float2 v0 = {acc[ni][0]+bb.x, acc[ni][1]+bb.y};
        float2 v1 = {acc[ni][2]+bb.x, acc[ni][3]+bb.y};
        *(float2*)(out + (size_t)row*HD + col) = v0;
        *(float2*)(out + (size_t)(row+8)*HD + col) = v1;
    }
}

// ---------------------------------------------------------------------------
extern "C" void kernel_launch(void* const* d_in, const int* in_sizes, int n_in,
                              void* d_out, int out_size) {
    const float* q  = (const float*)d_in[0];
    const float* k  = (const float*)d_in[1];
    const float* v  = (const float*)d_in[2];
    const float* wq = (const float*)d_in[3];
    const float* bq = (const float*)d_in[4];
    const float* wk = (const float*)d_in[5];
    const float* bk = (const float*)d_in[6];
    const float* wv = (const float*)d_in[7];
    const float* bv = (const float*)d_in[8];
    const float* wp = (const float*)d_in[9];
    const float* bp = (const float*)d_in[10];

    float* out  = (float*)d_out;
    float* attn = out + OUT_ELEMS;

    dim3 projGrid(NH, (BATCH*SEQ)/128, 3);            // (8, 32, 3) = 768 blocks
    proj_all_kernel<<<projGrid, 256>>>(q, k, v, wq, wk, wv, bq, bk, bv);

    dim3 scoreGrid(SEQ/128, SEQ/128, BH);             // (8, 8, 32)
    scores_exp_kernel<<<scoreGrid, 512>>>(attn);

    dim3 ctxGrid(SEQ/64, BH, QCHUNKS);                // (16, 32, 2)
    context_norm_kernel<<<ctxGrid, 256>>>(attn);

    outproj_kernel<<<(BATCH*SEQ)/32, 256>>>(wp, bp, out);  // 128 blocks
}